// round 5
// baseline (speedup 1.0000x reference)
#include <cuda_runtime.h>

// CosmosUnpatcher3d: one Haar IDWT level (2,24,9,256,256) -> slice -> (2,3,17,512,512).
// Combined tap c^3*sqrt(8) = 1 exactly: each 2x2x2 output block is the 8-point
// Walsh-Hadamard transform of the 8 band values at that (t,h,w).
//
// R5 = R1 per-thread body, but each block owns an 8-row h-chunk walked with a
// 4-iteration loop (2 rows / iteration). Sequential 8KB read runs per band and
// 16KB write runs per output plane per block -> fewer DRAM row activates.

#define BAND_STRIDE2 (3 * 9 * 256 * 128)   // band stride in float2 units

__device__ __forceinline__ void wht8(const float v0, const float v1, const float v2,
                                     const float v3, const float v4, const float v5,
                                     const float v6, const float v7, float o[8]) {
    float a0 = v0 + v1, a1 = v0 - v1;
    float a2 = v2 + v3, a3 = v2 - v3;
    float a4 = v4 + v5, a5 = v4 - v5;
    float a6 = v6 + v7, a7 = v6 - v7;
    float b0 = a0 + a2, b2 = a0 - a2;
    float b1 = a1 + a3, b3 = a1 - a3;
    float b4 = a4 + a6, b6 = a4 - a6;
    float b5 = a5 + a7, b7 = a5 - a7;
    o[0] = b0 + b4; o[4] = b0 - b4;
    o[1] = b1 + b5; o[5] = b1 - b5;
    o[2] = b2 + b6; o[6] = b2 - b6;
    o[3] = b3 + b7; o[7] = b3 - b7;
}

__global__ __launch_bounds__(256)
void idwt_haar_kernel(const float2* __restrict__ in, float* __restrict__ out) {
    // Grid: 54 * 32 = 1728 blocks. blockIdx.x = (bc*9 + t) * 32 + hc
    int hc = blockIdx.x & 31;          // h-chunk [0,32): rows 8*hc .. 8*hc+7
    int r  = blockIdx.x >> 5;          // (b*3+ch)*9 + t in [0,54)
    int bc = r / 9;                    // b*3 + ch
    int t  = r - bc * 9;
    int b  = bc / 3;
    int ch = bc - 3 * b;

    int wp   = threadIdx.x & 127;      // w-pair index [0,128)
    int hloc = threadIdx.x >> 7;       // 0 or 1
    int h0   = (hc << 3) + hloc;       // starting h for this thread

    // input base (float2 units) at h = h0: (((b*24+ch)*9+t)*256 + h0)*128 + wp
    int ibase = ((((b * 24 + ch) * 9 + t) << 8) + h0) * 128 + wp;

    // output base pieces
    int t2a = 2 * t - 1;               // pt=0 plane (skip if < 0)
    int t2b = 2 * t;                   // pt=1 plane
    int oplane_a = (bc * 17 + t2a) << 18;
    int oplane_b = (bc * 17 + t2b) << 18;

#pragma unroll
    for (int it = 0; it < 4; it++) {
        int ib = ibase + it * 256;     // +2 h rows = 2*128 float2
        int h  = h0 + 2 * it;

        float2 v0 = in[ib + 0 * BAND_STRIDE2];
        float2 v1 = in[ib + 1 * BAND_STRIDE2];
        float2 v2 = in[ib + 2 * BAND_STRIDE2];
        float2 v3 = in[ib + 3 * BAND_STRIDE2];
        float2 v4 = in[ib + 4 * BAND_STRIDE2];
        float2 v5 = in[ib + 5 * BAND_STRIDE2];
        float2 v6 = in[ib + 6 * BAND_STRIDE2];
        float2 v7 = in[ib + 7 * BAND_STRIDE2];

        float x[8], y[8];
        wht8(v0.x, v1.x, v2.x, v3.x, v4.x, v5.x, v6.x, v7.x, x);
        wht8(v0.y, v1.y, v2.y, v3.y, v4.y, v5.y, v6.y, v7.y, y);

        int orow0 = (((h << 1)) << 9) + (wp << 2);      // ph=0 row offset
        int orow1 = (((h << 1) + 1) << 9) + (wp << 2);  // ph=1 row offset

        if (t2a >= 0) {
            *(float4*)(out + oplane_a + orow0) = make_float4(x[0], x[1], y[0], y[1]);
            *(float4*)(out + oplane_a + orow1) = make_float4(x[2], x[3], y[2], y[3]);
        }
        *(float4*)(out + oplane_b + orow0) = make_float4(x[4], x[5], y[4], y[5]);
        *(float4*)(out + oplane_b + orow1) = make_float4(x[6], x[7], y[6], y[7]);
    }
}

extern "C" void kernel_launch(void* const* d_in, const int* in_sizes, int n_in,
                              void* d_out, int out_size) {
    const float2* in = (const float2*)d_in[0];
    float* out = (float*)d_out;
    idwt_haar_kernel<<<1728, 256>>>(in, out);
}

// round 6
// speedup vs baseline: 1.0434x; 1.0434x over previous
#include <cuda_runtime.h>

// CosmosUnpatcher3d: one Haar IDWT level (2,24,9,256,256) -> slice -> (2,3,17,512,512).
// Combined tap c^3*sqrt(8) = 1 exactly: each 2x2x2 output block is the 8-point
// Walsh-Hadamard transform of the 8 band values at that (t,h,w).
//
// R6 = R1 per-thread body exactly (32 regs, float2 loads, float4 stores,
// default cache policy), but 128-thread blocks (13824 blocks, 16/SM):
// finer CTA allocation granularity -> higher achieved occupancy / smoother
// wave transitions. Evidence R1-R5: DRAM% tracks achieved occupancy only.

#define BAND_STRIDE2 (3 * 9 * 256 * 128)   // band stride in float2 units

__device__ __forceinline__ void wht8(const float v0, const float v1, const float v2,
                                     const float v3, const float v4, const float v5,
                                     const float v6, const float v7, float o[8]) {
    float a0 = v0 + v1, a1 = v0 - v1;
    float a2 = v2 + v3, a3 = v2 - v3;
    float a4 = v4 + v5, a5 = v4 - v5;
    float a6 = v6 + v7, a7 = v6 - v7;
    float b0 = a0 + a2, b2 = a0 - a2;
    float b1 = a1 + a3, b3 = a1 - a3;
    float b4 = a4 + a6, b6 = a4 - a6;
    float b5 = a5 + a7, b7 = a5 - a7;
    o[0] = b0 + b4; o[4] = b0 - b4;
    o[1] = b1 + b5; o[5] = b1 - b5;
    o[2] = b2 + b6; o[6] = b2 - b6;
    o[3] = b3 + b7; o[7] = b3 - b7;
}

__global__ __launch_bounds__(128)
void idwt_haar_kernel(const float2* __restrict__ in, float* __restrict__ out) {
    int tid = blockIdx.x * 128 + threadIdx.x;
    // total threads = 2*3*9*256*128 = 1,769,472 (exact grid)
    int wp  = tid & 127;          // w-pair index [0,128)
    int h   = (tid >> 7) & 255;   // input h [0,256)
    int r   = tid >> 15;          // [0,54) = (b*3+ch)*9 + t
    int bc  = r / 9;              // b*3 + ch
    int t   = r - bc * 9;
    int b   = bc / 3;
    int ch  = bc - 3 * b;

    // input base in float2 units: (((b*24+ch)*9+t)*256 + h)*128 + wp
    int ibase = ((((b * 24 + ch) * 9 + t) << 8) + h) * 128 + wp;

    float2 v0 = in[ibase + 0 * BAND_STRIDE2];
    float2 v1 = in[ibase + 1 * BAND_STRIDE2];
    float2 v2 = in[ibase + 2 * BAND_STRIDE2];
    float2 v3 = in[ibase + 3 * BAND_STRIDE2];
    float2 v4 = in[ibase + 4 * BAND_STRIDE2];
    float2 v5 = in[ibase + 5 * BAND_STRIDE2];
    float2 v6 = in[ibase + 6 * BAND_STRIDE2];
    float2 v7 = in[ibase + 7 * BAND_STRIDE2];

    float x[8], y[8];
    wht8(v0.x, v1.x, v2.x, v3.x, v4.x, v5.x, v6.x, v7.x, x);
    wht8(v0.y, v1.y, v2.y, v3.y, v4.y, v5.y, v6.y, v7.y, y);

    // Output (2,3,17,512,512): t2 = 2t + pt - 1 (drop t2 < 0).
#pragma unroll
    for (int pt = 0; pt < 2; pt++) {
        int t2 = 2 * t + pt - 1;
        if (t2 < 0) continue;
#pragma unroll
        for (int ph = 0; ph < 2; ph++) {
            int p = pt * 4 + ph * 2;
            int obase = ((bc * 17 + t2) << 18) + (((h << 1) + ph) << 9) + (wp << 2);
            *(float4*)(out + obase) = make_float4(x[p], x[p + 1], y[p], y[p + 1]);
        }
    }
}

extern "C" void kernel_launch(void* const* d_in, const int* in_sizes, int n_in,
                              void* d_out, int out_size) {
    const float2* in = (const float2*)d_in[0];
    float* out = (float*)d_out;
    // 1,769,472 threads / 128 = 13824 blocks
    idwt_haar_kernel<<<13824, 128>>>(in, out);
}

// round 7
// speedup vs baseline: 1.0443x; 1.0009x over previous
#include <cuda_runtime.h>

// CosmosUnpatcher3d: one Haar IDWT level (2,24,9,256,256) -> slice -> (2,3,17,512,512).
// Combined tap c^3*sqrt(8) = 1 exactly: each 2x2x2 output block is the 8-point
// Walsh-Hadamard transform of the 8 band values at that (t,h,w).
//
// FINAL (R7 = R1 confirmed): one thread per input float2 per (b,ch,t,h).
//  - 8 coalesced float2 band loads (8 parallel streams, MLP=8)
//  - two register WHT-8 butterflies (24 FADD per 16 outputs)
//  - up to 4 coalesced float4 stores (512B/warp runs, full-line writes)
//  - 32 regs, 256-thread blocks, exact grid, default cache policy.
//
// Evidence R1-R6: traffic is irreducible (220MB, zero reuse); sustained
// 5.9TB/s = mixed read/write HBM ceiling. Cache hints (cs/cg), 16B loads,
// h-chunking, and 128-thread blocks were all neutral or regressions.

#define BAND_STRIDE2 (3 * 9 * 256 * 128)   // band stride in float2 units

__device__ __forceinline__ void wht8(const float v0, const float v1, const float v2,
                                     const float v3, const float v4, const float v5,
                                     const float v6, const float v7, float o[8]) {
    float a0 = v0 + v1, a1 = v0 - v1;
    float a2 = v2 + v3, a3 = v2 - v3;
    float a4 = v4 + v5, a5 = v4 - v5;
    float a6 = v6 + v7, a7 = v6 - v7;
    float b0 = a0 + a2, b2 = a0 - a2;
    float b1 = a1 + a3, b3 = a1 - a3;
    float b4 = a4 + a6, b6 = a4 - a6;
    float b5 = a5 + a7, b7 = a5 - a7;
    o[0] = b0 + b4; o[4] = b0 - b4;
    o[1] = b1 + b5; o[5] = b1 - b5;
    o[2] = b2 + b6; o[6] = b2 - b6;
    o[3] = b3 + b7; o[7] = b3 - b7;
}

__global__ __launch_bounds__(256)
void idwt_haar_kernel(const float* __restrict__ in, float* __restrict__ out) {
    int tid = blockIdx.x * 256 + threadIdx.x;
    // total threads = 2*3*9*256*128 = 1,769,472 (exact grid, no tail check)
    int wp = tid & 127;          // w-pair index [0,128)
    int h  = (tid >> 7) & 255;   // input h [0,256)
    int r  = tid >> 15;          // [0,54) = (b*3+ch)*9 + t
    int t  = r % 9;
    int bc = r / 9;              // b*3 + ch
    int b  = bc / 3;
    int ch = bc - 3 * b;

    // input base in float2 units
    int ibase2 = ((((b * 24 + ch) * 9 + t) << 16) + (h << 8) + (wp << 1)) >> 1;
    const float2* in2 = (const float2*)in;

    float2 v0 = in2[ibase2 + 0 * BAND_STRIDE2];
    float2 v1 = in2[ibase2 + 1 * BAND_STRIDE2];
    float2 v2 = in2[ibase2 + 2 * BAND_STRIDE2];
    float2 v3 = in2[ibase2 + 3 * BAND_STRIDE2];
    float2 v4 = in2[ibase2 + 4 * BAND_STRIDE2];
    float2 v5 = in2[ibase2 + 5 * BAND_STRIDE2];
    float2 v6 = in2[ibase2 + 6 * BAND_STRIDE2];
    float2 v7 = in2[ibase2 + 7 * BAND_STRIDE2];

    float x[8], y[8];
    wht8(v0.x, v1.x, v2.x, v3.x, v4.x, v5.x, v6.x, v7.x, x);
    wht8(v0.y, v1.y, v2.y, v3.y, v4.y, v5.y, v6.y, v7.y, y);

    // Output (2,3,17,512,512): t2 = 2t + pt - 1 (drop t2 < 0).
#pragma unroll
    for (int pt = 0; pt < 2; pt++) {
        int t2 = 2 * t + pt - 1;
        if (t2 < 0) continue;
#pragma unroll
        for (int ph = 0; ph < 2; ph++) {
            int p = pt * 4 + ph * 2;
            int obase = ((bc * 17 + t2) << 18) + (((h << 1) + ph) << 9) + (wp << 2);
            *(float4*)(out + obase) = make_float4(x[p], x[p + 1], y[p], y[p + 1]);
        }
    }
}

extern "C" void kernel_launch(void* const* d_in, const int* in_sizes, int n_in,
                              void* d_out, int out_size) {
    const float* in = (const float*)d_in[0];
    float* out = (float*)d_out;
    // 1,769,472 threads / 256 = 6912 blocks
    idwt_haar_kernel<<<6912, 256>>>(in, out);
}